// round 16
// baseline (speedup 1.0000x reference)
#include <cuda_runtime.h>
#include <cuda_bf16.h>
#include <cuda_fp16.h>
#include <cstdint>

#define N_NODES 8192
#define FIN 512
#define FOUT 256
#define ALPHA 0.2f
#define LOG2E 1.4426950408889634f

#if defined(__CUDA_ARCH__) && defined(__CUDA_ARCH_FEAT_SM103_ALL)
#define TC_ON 1
#else
#define TC_ON 0
#endif

#define SPLITS 4
#define JSPAN (N_NODES / SPLITS)   // 2048
#define KC 32
#define STAGES (JSPAN / KC)        // 64
#define TM 128                     // rows per CTA (2 CTAs/SM)
#define ATHREADS 256

// ---- scratch ----
__device__ float g_Wh[N_NODES * FOUT];                  // 8 MB
__device__ float g_f1[N_NODES];
__device__ float g_f2[N_NODES];
__device__ int   g_gmax_key;
__device__ __half g_WhT_hi[FOUT * N_NODES];             // 4 MB  [f][j]  fp16
__device__ float g_Up[(size_t)SPLITS * N_NODES * FOUT]; // 32 MB
__device__ float g_Zp[SPLITS * N_NODES];

typedef unsigned long long u64;

__device__ __forceinline__ u64 pack2(float lo, float hi) {
    u64 r; asm("mov.b64 %0, {%1, %2};" : "=l"(r) : "f"(lo), "f"(hi)); return r;
}
__device__ __forceinline__ void unpack2(u64 v, float& lo, float& hi) {
    asm("mov.b64 {%0, %1}, %2;" : "=f"(lo), "=f"(hi) : "l"(v));
}
__device__ __forceinline__ void ffma2(u64& d, u64 a, u64 b) {
    asm("fma.rn.f32x2 %0, %1, %2, %0;" : "+l"(d) : "l"(a), "l"(b));
}
__device__ __forceinline__ uint32_t smem_u32(const void* p) {
    uint32_t a;
    asm("{ .reg .u64 t; cvta.to.shared.u64 t, %1; cvt.u32.u64 %0, t; }" : "=r"(a) : "l"(p));
    return a;
}
// pack two fp32 -> fp16x2, first arg in LOW half (memory order j0,j1)
__device__ __forceinline__ uint32_t f16x2_pack(float lo, float hi) {
    uint32_t r; asm("cvt.rn.f16x2.f32 %0, %1, %2;" : "=r"(r) : "f"(hi), "f"(lo)); return r;
}
__device__ __forceinline__ uint32_t swz64(uint32_t off) { return off ^ ((off >> 3) & 0x30); }
__device__ __forceinline__ float gmax_decode(int k) {
    int b = (k >= 0) ? k : (k ^ 0x7FFFFFFF);
    return __int_as_float(b);
}

#define CP16(dst, src)    asm volatile("cp.async.cg.shared.global [%0], [%1], 16;" :: "r"(dst), "l"(src) : "memory")
#define CP_COMMIT()       asm volatile("cp.async.commit_group;" ::: "memory")
#define CP_WAIT1()        asm volatile("cp.async.wait_group 1;" ::: "memory")
#define CP_WAIT0()        asm volatile("cp.async.wait_group 0;" ::: "memory")

// ---------------------------------------------------------------------------
// Kernel 1: Wh = h @ W (fp32, f32x2 FMA) + fused transpose fp16 epilogue.
// ---------------------------------------------------------------------------
__global__ __launch_bounds__(256) void k_gemm_wh(const float* __restrict__ h,
                                                 const float* __restrict__ W) {
    if (blockIdx.x == 0 && blockIdx.y == 0 && threadIdx.x == 0)
        g_gmax_key = (int)0x80000000;
    __shared__ __align__(16) float As[16][66];
    __shared__ __align__(16) float Bs[16][64];
    __shared__ __align__(16) float S[64][65];
    const int bm = blockIdx.x * 64, bn = blockIdx.y * 64;
    const int tid = threadIdx.x;
    const int tx = tid & 15, ty = tid >> 4;
    u64 acc[2][4] = {};
    for (int k0 = 0; k0 < FIN; k0 += 16) {
        {
            int m = tid >> 2, kq = tid & 3;
            float4 v = *(const float4*)&h[(size_t)(bm + m) * FIN + k0 + kq * 4];
            As[kq * 4 + 0][m] = v.x; As[kq * 4 + 1][m] = v.y;
            As[kq * 4 + 2][m] = v.z; As[kq * 4 + 3][m] = v.w;
        }
        {
            int k = tid >> 4, n4 = tid & 15;
            *(float4*)&Bs[k][n4 * 4] = *(const float4*)&W[(size_t)(k0 + k) * FOUT + bn + n4 * 4];
        }
        __syncthreads();
        #pragma unroll
        for (int k = 0; k < 16; k++) {
            float4 b4 = *(const float4*)&Bs[k][tx * 4];
            u64 bx = pack2(b4.x, b4.x), by = pack2(b4.y, b4.y);
            u64 bz = pack2(b4.z, b4.z), bw = pack2(b4.w, b4.w);
            const u64* ap = (const u64*)&As[k][ty * 4];
            u64 a01 = ap[0], a23 = ap[1];
            ffma2(acc[0][0], a01, bx); ffma2(acc[0][1], a01, by);
            ffma2(acc[0][2], a01, bz); ffma2(acc[0][3], a01, bw);
            ffma2(acc[1][0], a23, bx); ffma2(acc[1][1], a23, by);
            ffma2(acc[1][2], a23, bz); ffma2(acc[1][3], a23, bw);
        }
        __syncthreads();
    }
    #pragma unroll
    for (int r = 0; r < 2; r++) {
        float e0, o0, e1, o1, e2, o2, e3, o3;
        unpack2(acc[r][0], e0, o0); unpack2(acc[r][1], e1, o1);
        unpack2(acc[r][2], e2, o2); unpack2(acc[r][3], e3, o3);
        int r0 = ty * 4 + 2 * r, r1 = r0 + 1;
        *(float4*)&g_Wh[(size_t)(bm + r0) * FOUT + bn + tx * 4] = make_float4(e0, e1, e2, e3);
        *(float4*)&g_Wh[(size_t)(bm + r1) * FOUT + bn + tx * 4] = make_float4(o0, o1, o2, o3);
        S[r0][tx * 4 + 0] = e0; S[r0][tx * 4 + 1] = e1; S[r0][tx * 4 + 2] = e2; S[r0][tx * 4 + 3] = e3;
        S[r1][tx * 4 + 0] = o0; S[r1][tx * 4 + 1] = o1; S[r1][tx * 4 + 2] = o2; S[r1][tx * 4 + 3] = o3;
    }
    __syncthreads();
    {
        const int fl = tid >> 2, jq = (tid & 3) * 16;
        uint32_t hw[8];
        #pragma unroll
        for (int c = 0; c < 8; c++)
            hw[c] = f16x2_pack(S[jq + 2 * c][fl], S[jq + 2 * c + 1][fl]);
        size_t base = (size_t)(bn + fl) * N_NODES + bm + jq;
        *(uint4*)&g_WhT_hi[base]     = make_uint4(hw[0], hw[1], hw[2], hw[3]);
        *(uint4*)&g_WhT_hi[base + 8] = make_uint4(hw[4], hw[5], hw[6], hw[7]);
    }
}

// ---------------------------------------------------------------------------
// Kernel 2: f1/f2 row dots + atomic gmax
// ---------------------------------------------------------------------------
__global__ __launch_bounds__(256) void k_f12(const float* __restrict__ a) {
    int warp = (blockIdx.x * blockDim.x + threadIdx.x) >> 5;
    int lane = threadIdx.x & 31;
    if (warp >= N_NODES) return;
    const float* wh = &g_Wh[(size_t)warp * FOUT];
    float s1 = 0.f, s2 = 0.f;
    #pragma unroll
    for (int k = 0; k < FOUT; k += 32) {
        float v = wh[k + lane];
        s1 += v * a[k + lane];
        s2 += v * a[FOUT + k + lane];
    }
    #pragma unroll
    for (int o = 16; o; o >>= 1) {
        s1 += __shfl_xor_sync(~0u, s1, o);
        s2 += __shfl_xor_sync(~0u, s2, o);
    }
    if (!lane) {
        g_f1[warp] = s1; g_f2[warp] = s2;
        int i = __float_as_int(s2);
        int key = (i >= 0) ? i : (i ^ 0x7FFFFFFF);
        atomicMax(&g_gmax_key, key);
    }
}

// ===========================================================================
// ===================== TENSOR-CORE PATH (sm_103a only) =====================
// ===========================================================================
// Per-CTA SMEM: 3 x 24KB buffers [A 8KB | B 16KB], E-table 16KB, mbars, ptr.
// ~88 KB -> 2 CTAs per SM (each owns 256 TMEM cols).
#define BUF_SZ   24576
#define AH_O     0
#define BH_O     8192
#define ET_O     73728
#define MB_O     90112
#define TP_O     90144
#define TC_SMEM  90160

#if TC_ON
static constexpr uint64_t DESC_BASE_SW64 =
    (uint64_t(4) << 61) | (uint64_t(1) << 46) | (uint64_t(32) << 32) | (uint64_t(1) << 16);
__device__ __forceinline__ uint64_t mk_desc64(uint32_t addr) {
    return DESC_BASE_SW64 | ((uint64_t)(addr >> 4) & 0x3FFF);
}
__device__ __forceinline__ void mma_f16_ss(uint32_t d, uint64_t ad, uint64_t bd,
                                           uint32_t idesc, uint32_t en) {
    asm volatile(
        "{\n\t.reg .pred p;\n\t"
        "setp.ne.u32 p, %5, 0;\n\t"
        "tcgen05.mma.cta_group::1.kind::f16 [%0], %1, %2, %3, {%4, %4, %4, %4}, p;\n\t}"
        :: "r"(d), "l"(ad), "l"(bd), "r"(idesc), "r"(0u), "r"(en) : "memory");
}
#define TC_ALLOC(sa, n)   asm volatile("tcgen05.alloc.cta_group::1.sync.aligned.shared::cta.b32 [%0], %1;" :: "r"(sa), "r"(n) : "memory")
#define TC_DEALLOC(t, n)  asm volatile("tcgen05.dealloc.cta_group::1.sync.aligned.b32 %0, %1;" :: "r"(t), "r"(n))
#define TC_RELINQ()       asm volatile("tcgen05.relinquish_alloc_permit.cta_group::1.sync.aligned;")
#define TC_COMMIT(mb)     asm volatile("tcgen05.commit.cta_group::1.mbarrier::arrive::one.shared::cluster.b64 [%0];" :: "r"(mb) : "memory")
#define TC_WAIT_LD()      asm volatile("tcgen05.wait::ld.sync.aligned;" ::: "memory")
#define TC_FENCE_AFTER()  asm volatile("tcgen05.fence::after_thread_sync;" ::: "memory")
#define FENCE_PROXY()     asm volatile("fence.proxy.async;" ::: "memory")
#define MBAR_INIT(mb, n)  asm volatile("mbarrier.init.shared.b64 [%0], %1;" :: "r"(mb), "r"(n) : "memory")
#define MBAR_WAIT(mb, ph) do {                                                            \
    uint32_t _m = (mb), _p = (ph), _d;                                                    \
    asm volatile("{\n\t.reg .pred p;\n\t"                                                 \
        "mbarrier.try_wait.parity.acquire.cta.shared::cta.b64 p, [%1], %2;\n\t"           \
        "selp.b32 %0, 1, 0, p;\n\t}" : "=r"(_d) : "r"(_m), "r"(_p) : "memory");           \
    if (!_d) {                                                                            \
        asm volatile("{\n\t.reg .pred P1;\n\t"                                            \
            "W%=:\n\t"                                                                    \
            "mbarrier.try_wait.parity.acquire.cta.shared::cta.b64 P1, [%0], %1, 0x989680;\n\t" \
            "@P1 bra.uni D%=;\n\t"                                                        \
            "bra.uni W%=;\n\t"                                                            \
            "D%=:\n\t}" :: "r"(_m), "r"(_p) : "memory");                                  \
    }                                                                                     \
} while (0)
#define STS128A(a, r0, r1, r2, r3) asm volatile("st.shared.v4.b32 [%0], {%1,%2,%3,%4};" :: "r"(a), "r"(r0), "r"(r1), "r"(r2), "r"(r3) : "memory")
#define LDTM_X16(r, t) \
    asm volatile("tcgen05.ld.sync.aligned.32x32b.x16.b32 " \
        "{%0,%1,%2,%3,%4,%5,%6,%7,%8,%9,%10,%11,%12,%13,%14,%15}, [%16];" \
        : "=r"((r)[0]),"=r"((r)[1]),"=r"((r)[2]),"=r"((r)[3]), \
          "=r"((r)[4]),"=r"((r)[5]),"=r"((r)[6]),"=r"((r)[7]), \
          "=r"((r)[8]),"=r"((r)[9]),"=r"((r)[10]),"=r"((r)[11]), \
          "=r"((r)[12]),"=r"((r)[13]),"=r"((r)[14]),"=r"((r)[15]) \
        : "r"(t))

// idesc: F32 out | F16 a | F16 b | N=256 | M=128
static constexpr uint32_t IDESC =
    (1u << 4) | ((FOUT / 8) << 17) | (8u << 24);

// ---------------------------------------------------------------------------
// Attention: 256 CTAs = 64 row-blocks (TM=128) x 4 j-splits, 2 CTAs/SM.
// Pairing: split = blk>>6 so co-resident CTAs share the same B stream (L2).
// Thread -> (row = tid>>1, half = tid&1): 16 j per stage. Single fp16 MMA pass.
// ---------------------------------------------------------------------------
__global__ __launch_bounds__(ATHREADS, 2) void k_attn_tc(const int* __restrict__ adj) {
    extern __shared__ __align__(1024) char smem_raw[];
    const uint32_t sb = smem_u32(smem_raw);
    const int tid = threadIdx.x;
    const int wid = tid >> 5;
    const int split = blockIdx.x >> 6;
    const int i0 = (blockIdx.x & 63) * TM;
    const int jbase = split * JSPAN;

    if (wid == 0) TC_ALLOC(sb + TP_O, 256);
    if (tid == 0) {
        MBAR_INIT(sb + MB_O + 0, 1);
        MBAR_INIT(sb + MB_O + 8, 1);
        MBAR_INIT(sb + MB_O + 16, 1);
    }
    // E-table: et[j] = (exp(f2_j), exp(0.2*f2_j)), 2048 j = 16 KB
    float2* et = (float2*)(smem_raw + ET_O);
    #pragma unroll
    for (int q = 0; q < 2; q++) {
        float4 f2v = *(const float4*)&g_f2[jbase + tid * 8 + q * 4];
        float4 lo4, hi4;
        lo4.x = exp2f(f2v.x * LOG2E);          lo4.y = exp2f(f2v.x * (ALPHA * LOG2E));
        lo4.z = exp2f(f2v.y * LOG2E);          lo4.w = exp2f(f2v.y * (ALPHA * LOG2E));
        hi4.x = exp2f(f2v.z * LOG2E);          hi4.y = exp2f(f2v.z * (ALPHA * LOG2E));
        hi4.z = exp2f(f2v.w * LOG2E);          hi4.w = exp2f(f2v.w * (ALPHA * LOG2E));
        *(float4*)&et[tid * 8 + q * 4]     = lo4;
        *(float4*)&et[tid * 8 + q * 4 + 2] = hi4;
    }
    __syncthreads();
    const uint32_t tmem = *(const uint32_t*)(smem_raw + TP_O);

    const int row = tid >> 1, half = tid & 1;
    const float f1r = g_f1[i0 + row];
    const float gm = gmax_decode(g_gmax_key);
    const float Ms = f1r + gm;
    const float M = fmaxf(Ms, ALPHA * Ms);
    const float Ai = exp2f((f1r - M) * LOG2E);
    const float Ci = exp2f((ALPHA * f1r - M) * LOG2E);
    const int* adjrow = adj + (size_t)(i0 + row) * N_NODES + jbase + half * 16;
    float zreg = 0.f;

    // B cp.async mapping: thread tid covers f = tid, full 64B row (4 x 16B)
    // prologue: B(0) -> buf0
    {
        const char* sh = (const char*)&g_WhT_hi[(size_t)tid * N_NODES + jbase];
        #pragma unroll
        for (int q = 0; q < 4; q++)
            CP16(sb + BH_O + swz64((uint32_t)(tid * 64 + q * 16)), sh + q * 16);
        CP_COMMIT();
    }
    int4 areg[4];
    {
        const int4* ap = (const int4*)adjrow;
        #pragma unroll
        for (int q = 0; q < 4; q++) areg[q] = ap[q];
    }

    for (int s = 0; s < STAGES; s++) {
        const int b = s % 3;
        const int bn = (s + 1) % 3;

        // buffer bn free once MMA(s-2) committed
        if (s >= 2) MBAR_WAIT(sb + MB_O + bn * 8, ((s - 2) / 3) & 1);

        if (s + 1 < STAGES) {
            const size_t jcol = (size_t)jbase + (s + 1) * KC;
            const uint32_t bh = sb + bn * BUF_SZ + BH_O;
            const char* sh = (const char*)&g_WhT_hi[(size_t)tid * N_NODES + jcol];
            #pragma unroll
            for (int q = 0; q < 4; q++)
                CP16(bh + swz64((uint32_t)(tid * 64 + q * 16)), sh + q * 16);
        }
        CP_COMMIT();

        // P tile: 16 j, factorized-exp + max trick, fp16 store
        {
            const uint32_t ah = sb + b * BUF_SZ + AH_O;
            const float4* ev = (const float4*)&et[s * KC + half * 16];
            #pragma unroll
            for (int t2 = 0; t2 < 2; t2++) {
                float p[8];
                #pragma unroll
                for (int q = 0; q < 2; q++) {
                    float4 e0 = ev[t2 * 4 + q * 2];
                    float4 e1 = ev[t2 * 4 + q * 2 + 1];
                    int4 av = areg[t2 * 2 + q];
                    float p0 = fmaxf(e0.x * Ai, e0.y * Ci);
                    float p1 = fmaxf(e0.z * Ai, e0.w * Ci);
                    float p2 = fmaxf(e1.x * Ai, e1.y * Ci);
                    float p3 = fmaxf(e1.z * Ai, e1.w * Ci);
                    p[q * 4 + 0] = (av.x > 0) ? p0 : 0.f;
                    p[q * 4 + 1] = (av.y > 0) ? p1 : 0.f;
                    p[q * 4 + 2] = (av.z > 0) ? p2 : 0.f;
                    p[q * 4 + 3] = (av.w > 0) ? p3 : 0.f;
                    zreg += p[q * 4 + 0] + p[q * 4 + 1] + p[q * 4 + 2] + p[q * 4 + 3];
                }
                uint32_t hw0 = f16x2_pack(p[0], p[1]);
                uint32_t hw1 = f16x2_pack(p[2], p[3]);
                uint32_t hw2 = f16x2_pack(p[4], p[5]);
                uint32_t hw3 = f16x2_pack(p[6], p[7]);
                uint32_t so = swz64((uint32_t)(row * 64 + half * 32 + t2 * 16));
                STS128A(ah + so, hw0, hw1, hw2, hw3);
            }
        }

        if (s + 1 < STAGES) {
            const int4* ap = (const int4*)(adjrow + (size_t)(s + 1) * KC);
            #pragma unroll
            for (int q = 0; q < 4; q++) areg[q] = ap[q];
        }

        CP_WAIT1();
        __syncthreads();

        if (tid == 0) {
            FENCE_PROXY();
            const uint32_t ab = sb + b * BUF_SZ;
            uint64_t dah = mk_desc64(ab + AH_O);
            uint64_t dbh = mk_desc64(ab + BH_O);
            #pragma unroll
            for (int k = 0; k < 2; k++) {
                uint32_t en = !(s == 0 && k == 0);
                mma_f16_ss(tmem, dah + k * 2, dbh + k * 2, IDESC, en);
            }
            TC_COMMIT(sb + MB_O + b * 8);
        }
    }

    zreg += __shfl_xor_sync(~0u, zreg, 1);
    if (!half) g_Zp[split * N_NODES + i0 + row] = zreg;

    MBAR_WAIT(sb + MB_O + ((STAGES - 1) % 3) * 8, ((STAGES - 1) / 3) & 1);
    TC_FENCE_AFTER();

    // readout: 8 warps; subpartition sw = wid&3 (rows sw*32+lane), colhalf = wid>>2
    {
        const int sw = wid & 3;
        const int colhalf = wid >> 2;
        const int lane = tid & 31;
        float* up = &g_Up[((size_t)split * N_NODES + i0 + sw * 32 + lane) * FOUT
                          + colhalf * 128];
        const uint32_t tbase = tmem + colhalf * 128;
        #pragma unroll
        for (int cb = 0; cb < 128; cb += 16) {
            uint32_t r[16];
            LDTM_X16(r, tbase + cb);
            TC_WAIT_LD();
            #pragma unroll
            for (int c = 0; c < 16; c += 4)
                *(float4*)&up[cb + c] = make_float4(
                    __uint_as_float(r[c]), __uint_as_float(r[c + 1]),
                    __uint_as_float(r[c + 2]), __uint_as_float(r[c + 3]));
        }
    }
    __syncthreads();
    if (wid == 0) { TC_RELINQ(); TC_DEALLOC(tmem, 256); }
}

// TC mode: combine + ELU. grid 1024 x 256thr; 8 rows/block; 2 float4 outs/thread,
// each needing 4 independent LDG.128 (MLP 8).
__global__ __launch_bounds__(256, 4) void k_attn_fb(const int* __restrict__ adj,
                                                    float* __restrict__ out) {
    __shared__ float invz[8];
    const size_t NF = (size_t)N_NODES * FOUT;
    const int i0 = blockIdx.x * 8;
    const int tid = threadIdx.x;
    if (tid < 8) {
        int r = i0 + tid;
        float z = g_Zp[r] + g_Zp[N_NODES + r] + g_Zp[2 * N_NODES + r] + g_Zp[3 * N_NODES + r];
        invz[tid] = 1.f / z;
    }
    __syncthreads();
    #pragma unroll
    for (int k = 0; k < 2; k++) {
        int lin = tid + k * 256;
        int r = lin >> 6, c4 = (lin & 63) * 4;
        size_t off = (size_t)(i0 + r) * FOUT + c4;
        float4 u0 = *(const float4*)&g_Up[off];
        float4 u1 = *(const float4*)&g_Up[NF + off];
        float4 u2 = *(const float4*)&g_Up[2 * NF + off];
        float4 u3 = *(const float4*)&g_Up[3 * NF + off];
        float iz = invz[r];
        float4 v;
        v.x = (u0.x + u1.x + u2.x + u3.x) * iz;
        v.y = (u0.y + u1.y + u2.y + u3.y) * iz;
        v.z = (u0.z + u1.z + u2.z + u3.z) * iz;
        v.w = (u0.w + u1.w + u2.w + u3.w) * iz;
        v.x = v.x > 0.f ? v.x : expm1f(v.x);
        v.y = v.y > 0.f ? v.y : expm1f(v.y);
        v.z = v.z > 0.f ? v.z : expm1f(v.z);
        v.w = v.w > 0.f ? v.w : expm1f(v.w);
        *(float4*)&out[off] = v;
    }
}

#else  // ================== CUDA-CORE FALLBACK PATH ==========================

__global__ __launch_bounds__(ATHREADS, 2) void k_attn_tc(const int* __restrict__ adj) {}

#define FB_WHS(buf) ((buf) * 8192)
#define FB_PS(buf)  (16384 + (buf) * 1152)
#define FB_ZR       18688

__global__ __launch_bounds__(256, 2) void k_attn_fb(const int* __restrict__ adj,
                                                    float* __restrict__ out) {
    extern __shared__ __align__(16) float fsm[];
    const uint32_t sb = smem_u32(fsm);
    const int tid = threadIdx.x;
    const int i0 = blockIdx.x * 32;
    if (i0 >= N_NODES) return;   // wide grid in tc mode
    const int tx = tid & 63;
    const int ty = tid >> 6;
    const int pr = tid >> 3;
    const int pc = (tid & 7) * 4;

    const float f1r = g_f1[i0 + pr];
    const float gm = gmax_decode(g_gmax_key);
    const float Ms = f1r + gm;
    const float M = fmaxf(Ms, ALPHA * Ms);
    const size_t arowbase = (size_t)(i0 + pr) * N_NODES;

    u64 acc[4][4] = {};
    float zreg = 0.f;

    {
        #pragma unroll
        for (int l = 0; l < 8; l++) {
            int lin = l * 256 + tid;
            int row = lin >> 6, c4 = lin & 63;
            CP16(sb + (uint32_t)(FB_WHS(0) + row * 256 + c4 * 4) * 4,
                 (const char*)&g_Wh[(size_t)row * FOUT + c4 * 4]);
        }
        CP_COMMIT();
        int4 av = *(const int4*)(adj + arowbase + pc);
        float4 fv = *(const float4*)&g_f2[pc];
        const int am[4] = {av.x, av.y, av.z, av.w};
        const float ff[4] = {fv.x, fv.y, fv.z, fv.w};
        #pragma unroll
        for (int c = 0; c < 4; c++) {
            float e = f1r + ff[c];
            e = fmaxf(e, ALPHA * e);
            float p = (am[c] > 0) ? __expf(e - M) : 0.f;
            zreg += p;
            fsm[FB_PS(0) + (pc + c) * 36 + pr] = p;
        }
        CP_WAIT0();
        __syncthreads();
    }

    for (int s = 0; s < 256; s++) {
        const int cur = s & 1;
        int4 a_pf; float4 f2_pf;
        const bool more = (s < 255);
        if (more) {
            const int j0n = (s + 1) * 32;
            #pragma unroll
            for (int l = 0; l < 8; l++) {
                int lin = l * 256 + tid;
                int row = lin >> 6, c4 = lin & 63;
                CP16(sb + (uint32_t)(FB_WHS(cur ^ 1) + row * 256 + c4 * 4) * 4,
                     (const char*)&g_Wh[(size_t)(j0n + row) * FOUT + c4 * 4]);
            }
            CP_COMMIT();
            a_pf = *(const int4*)(adj + arowbase + j0n + pc);
            f2_pf = *(const float4*)&g_f2[j0n + pc];
        }

        const float* Whc = &fsm[FB_WHS(cur)];
        const float* Psc = &fsm[FB_PS(cur)];
        #pragma unroll
        for (int jj = 0; jj < 32; jj++) {
            const u64* pp = (const u64*)&Psc[jj * 36 + ty * 8];
            u64 p01 = pp[0], p23 = pp[1], p45 = pp[2], p67 = pp[3];
            float4 w4 = *(const float4*)&Whc[jj * 256 + tx * 4];
            u64 wx = pack2(w4.x, w4.x), wy = pack2(w4.y, w4.y);
            u64 wz = pack2(w4.z, w4.z), ww = pack2(w4.w, w4.w);
            ffma2(acc[0][0], p01, wx); ffma2(acc[0][1], p01, wy);
            ffma2(acc[0][2], p01, wz); ffma2(acc[0][3], p01, ww);
            ffma2(acc[1][0], p23, wx); ffma2(acc[1][1], p23, wy);
            ffma2(acc[1][2], p23, wz); ffma2(acc[1][3], p23, ww);
            ffma2(acc[2][0], p45, wx); ffma2(acc[2][1], p45, wy);
            ffma2(acc[2][2], p45, wz); ffma2(acc[2][3], p45, ww);
            ffma2(acc[3][0], p67, wx); ffma2(acc[3][1], p67, wy);
            ffma2(acc[3][2], p67, wz); ffma2(acc[3][3], p67, ww);
        }

        if (more) {
            const int am[4] = {a_pf.x, a_pf.y, a_pf.z, a_pf.w};
            const float ff[4] = {f2_pf.x, f2_pf.y, f2_pf.z, f2_pf.w};
            #pragma unroll
            for (int c = 0; c < 4; c++) {
                float e = f1r + ff[c];
                e = fmaxf(e, ALPHA * e);
                float p = (am[c] > 0) ? __expf(e - M) : 0.f;
                zreg += p;
                fsm[FB_PS(cur ^ 1) + (pc + c) * 36 + pr] = p;
            }
            CP_WAIT0();
        }
        __syncthreads();
    }

    zreg += __shfl_xor_sync(~0u, zreg, 4);
    zreg += __shfl_xor_sync(~0u, zreg, 2);
    zreg += __shfl_xor_sync(~0u, zreg, 1);
    if ((tid & 7) == 0) fsm[FB_ZR + pr] = zreg;
    __syncthreads();

    #pragma unroll
    for (int r = 0; r < 4; r++) {
        int row_e = ty * 8 + 2 * r;
        float invZe = 1.f / fsm[FB_ZR + row_e];
        float invZo = 1.f / fsm[FB_ZR + row_e + 1];
        float e0, o0, e1, o1, e2, o2, e3, o3;
        unpack2(acc[r][0], e0, o0); unpack2(acc[r][1], e1, o1);
        unpack2(acc[r][2], e2, o2); unpack2(acc[r][3], e3, o3);
        e0 *= invZe; e1 *= invZe; e2 *= invZe; e3 *= invZe;
        o0 *= invZo; o1 *= invZo; o2 *= invZo; o3 *= invZo;
        float4 ve, vo;
        ve.x = e0 > 0.f ? e0 : expm1f(e0);
        ve.y = e1 > 0.f ? e1 : expm1f(e1);
        ve.z = e2 > 0.f ? e2 : expm1f(e2);
        ve.w = e3 > 0.f ? e3 : expm1f(e3);
        vo.x = o0 > 0.f ? o0 : expm1f(o0);
        vo.y = o1 > 0.f ? o1 : expm1f(o1);
        vo.z = o2 > 0.f ? o2 : expm1f(o2);
        vo.w = o3 > 0.f ? o3 : expm1f(o3);
        *(float4*)&out[(size_t)(i0 + row_e + 0) * FOUT + tx * 4] = ve;
        *(float4*)&out[(size_t)(i0 + row_e + 1) * FOUT + tx * 4] = vo;
    }
}
#endif  // TC_ON

#define FB_SMEM 74880

// ---------------------------------------------------------------------------
extern "C" void kernel_launch(void* const* d_in, const int* in_sizes, int n_in,
                              void* d_out, int out_size) {
    const float* h   = (const float*)d_in[0];
    const int*   adj = (const int*)d_in[1];
    const float* W   = (const float*)d_in[2];
    const float* a   = (const float*)d_in[3];
    float* out = (float*)d_out;

    cudaFuncSetAttribute(k_attn_tc, cudaFuncAttributeMaxDynamicSharedMemorySize, TC_SMEM);
    cudaFuncSetAttribute(k_attn_fb, cudaFuncAttributeMaxDynamicSharedMemorySize, FB_SMEM);

    dim3 g1(N_NODES / 64, FOUT / 64);
    k_gemm_wh<<<g1, 256>>>(h, W);                                    // + fused fp16 split
    k_f12<<<N_NODES / 8, 256>>>(a);
    k_attn_tc<<<(N_NODES / TM) * SPLITS, ATHREADS, TC_SMEM>>>(adj);  // 256 CTAs, 2/SM
    k_attn_fb<<<N_NODES / 8, 256, FB_SMEM>>>(adj, out);              // combiner (tc) / full fb
}

// round 17
// speedup vs baseline: 1.3653x; 1.3653x over previous
#include <cuda_runtime.h>
#include <cuda_bf16.h>
#include <cuda_fp16.h>
#include <cstdint>

#define N_NODES 8192
#define FIN 512
#define FOUT 256
#define ALPHA 0.2f
#define LOG2E 1.4426950408889634f

#if defined(__CUDA_ARCH__) && defined(__CUDA_ARCH_FEAT_SM103_ALL)
#define TC_ON 1
#else
#define TC_ON 0
#endif

#define SPLITS 4
#define JSPAN (N_NODES / SPLITS)   // 2048
#define KC 32
#define STAGES (JSPAN / KC)        // 64
#define TM 256
#define ATHREADS 512

// ---- scratch ----
__device__ float g_Wh[N_NODES * FOUT];                  // 8 MB
__device__ float g_f1[N_NODES];
__device__ float g_f2[N_NODES];
__device__ int   g_gmax_key;
__device__ __half g_WhT_hi[FOUT * N_NODES];             // 4 MB  [f][j]  fp16
__device__ float g_Up[(size_t)SPLITS * N_NODES * FOUT]; // 32 MB
__device__ float g_Zp[SPLITS * N_NODES];

typedef unsigned long long u64;

__device__ __forceinline__ u64 pack2(float lo, float hi) {
    u64 r; asm("mov.b64 %0, {%1, %2};" : "=l"(r) : "f"(lo), "f"(hi)); return r;
}
__device__ __forceinline__ void unpack2(u64 v, float& lo, float& hi) {
    asm("mov.b64 {%0, %1}, %2;" : "=f"(lo), "=f"(hi) : "l"(v));
}
__device__ __forceinline__ void ffma2(u64& d, u64 a, u64 b) {
    asm("fma.rn.f32x2 %0, %1, %2, %0;" : "+l"(d) : "l"(a), "l"(b));
}
__device__ __forceinline__ uint32_t smem_u32(const void* p) {
    uint32_t a;
    asm("{ .reg .u64 t; cvta.to.shared.u64 t, %1; cvt.u32.u64 %0, t; }" : "=r"(a) : "l"(p));
    return a;
}
// pack two fp32 -> fp16x2, first arg in LOW half (memory order j0,j1)
__device__ __forceinline__ uint32_t f16x2_pack(float lo, float hi) {
    uint32_t r; asm("cvt.rn.f16x2.f32 %0, %1, %2;" : "=r"(r) : "f"(hi), "f"(lo)); return r;
}
__device__ __forceinline__ uint32_t swz64(uint32_t off) { return off ^ ((off >> 3) & 0x30); }
__device__ __forceinline__ float gmax_decode(int k) {
    int b = (k >= 0) ? k : (k ^ 0x7FFFFFFF);
    return __int_as_float(b);
}

#define CP16(dst, src)    asm volatile("cp.async.cg.shared.global [%0], [%1], 16;" :: "r"(dst), "l"(src) : "memory")
#define CP_COMMIT()       asm volatile("cp.async.commit_group;" ::: "memory")
#define CP_WAIT1()        asm volatile("cp.async.wait_group 1;" ::: "memory")
#define CP_WAIT0()        asm volatile("cp.async.wait_group 0;" ::: "memory")

// ---------------------------------------------------------------------------
// Kernel 1: Wh = h @ W (fp32, f32x2 FMA) + fused transpose fp16 epilogue.
// ---------------------------------------------------------------------------
__global__ __launch_bounds__(256) void k_gemm_wh(const float* __restrict__ h,
                                                 const float* __restrict__ W) {
    if (blockIdx.x == 0 && blockIdx.y == 0 && threadIdx.x == 0)
        g_gmax_key = (int)0x80000000;
    __shared__ __align__(16) float As[16][66];
    __shared__ __align__(16) float Bs[16][64];
    __shared__ __align__(16) float S[64][65];
    const int bm = blockIdx.x * 64, bn = blockIdx.y * 64;
    const int tid = threadIdx.x;
    const int tx = tid & 15, ty = tid >> 4;
    u64 acc[2][4] = {};
    for (int k0 = 0; k0 < FIN; k0 += 16) {
        {
            int m = tid >> 2, kq = tid & 3;
            float4 v = *(const float4*)&h[(size_t)(bm + m) * FIN + k0 + kq * 4];
            As[kq * 4 + 0][m] = v.x; As[kq * 4 + 1][m] = v.y;
            As[kq * 4 + 2][m] = v.z; As[kq * 4 + 3][m] = v.w;
        }
        {
            int k = tid >> 4, n4 = tid & 15;
            *(float4*)&Bs[k][n4 * 4] = *(const float4*)&W[(size_t)(k0 + k) * FOUT + bn + n4 * 4];
        }
        __syncthreads();
        #pragma unroll
        for (int k = 0; k < 16; k++) {
            float4 b4 = *(const float4*)&Bs[k][tx * 4];
            u64 bx = pack2(b4.x, b4.x), by = pack2(b4.y, b4.y);
            u64 bz = pack2(b4.z, b4.z), bw = pack2(b4.w, b4.w);
            const u64* ap = (const u64*)&As[k][ty * 4];
            u64 a01 = ap[0], a23 = ap[1];
            ffma2(acc[0][0], a01, bx); ffma2(acc[0][1], a01, by);
            ffma2(acc[0][2], a01, bz); ffma2(acc[0][3], a01, bw);
            ffma2(acc[1][0], a23, bx); ffma2(acc[1][1], a23, by);
            ffma2(acc[1][2], a23, bz); ffma2(acc[1][3], a23, bw);
        }
        __syncthreads();
    }
    #pragma unroll
    for (int r = 0; r < 2; r++) {
        float e0, o0, e1, o1, e2, o2, e3, o3;
        unpack2(acc[r][0], e0, o0); unpack2(acc[r][1], e1, o1);
        unpack2(acc[r][2], e2, o2); unpack2(acc[r][3], e3, o3);
        int r0 = ty * 4 + 2 * r, r1 = r0 + 1;
        *(float4*)&g_Wh[(size_t)(bm + r0) * FOUT + bn + tx * 4] = make_float4(e0, e1, e2, e3);
        *(float4*)&g_Wh[(size_t)(bm + r1) * FOUT + bn + tx * 4] = make_float4(o0, o1, o2, o3);
        S[r0][tx * 4 + 0] = e0; S[r0][tx * 4 + 1] = e1; S[r0][tx * 4 + 2] = e2; S[r0][tx * 4 + 3] = e3;
        S[r1][tx * 4 + 0] = o0; S[r1][tx * 4 + 1] = o1; S[r1][tx * 4 + 2] = o2; S[r1][tx * 4 + 3] = o3;
    }
    __syncthreads();
    {
        const int fl = tid >> 2, jq = (tid & 3) * 16;
        uint32_t hw[8];
        #pragma unroll
        for (int c = 0; c < 8; c++)
            hw[c] = f16x2_pack(S[jq + 2 * c][fl], S[jq + 2 * c + 1][fl]);
        size_t base = (size_t)(bn + fl) * N_NODES + bm + jq;
        *(uint4*)&g_WhT_hi[base]     = make_uint4(hw[0], hw[1], hw[2], hw[3]);
        *(uint4*)&g_WhT_hi[base + 8] = make_uint4(hw[4], hw[5], hw[6], hw[7]);
    }
}

// ---------------------------------------------------------------------------
// Kernel 2: f1/f2 row dots + atomic gmax
// ---------------------------------------------------------------------------
__global__ __launch_bounds__(256) void k_f12(const float* __restrict__ a) {
    int warp = (blockIdx.x * blockDim.x + threadIdx.x) >> 5;
    int lane = threadIdx.x & 31;
    if (warp >= N_NODES) return;
    const float* wh = &g_Wh[(size_t)warp * FOUT];
    float s1 = 0.f, s2 = 0.f;
    #pragma unroll
    for (int k = 0; k < FOUT; k += 32) {
        float v = wh[k + lane];
        s1 += v * a[k + lane];
        s2 += v * a[FOUT + k + lane];
    }
    #pragma unroll
    for (int o = 16; o; o >>= 1) {
        s1 += __shfl_xor_sync(~0u, s1, o);
        s2 += __shfl_xor_sync(~0u, s2, o);
    }
    if (!lane) {
        g_f1[warp] = s1; g_f2[warp] = s2;
        int i = __float_as_int(s2);
        int key = (i >= 0) ? i : (i ^ 0x7FFFFFFF);
        atomicMax(&g_gmax_key, key);
    }
}

// ===========================================================================
// ===================== TENSOR-CORE PATH (sm_103a only) =====================
// ===========================================================================
// Per-CTA SMEM: 3 x 32KB buffers [A 16KB | B 16KB], E-table 16KB, mbars, ptr.
#define BUF_SZ   32768
#define AH_O     0
#define BH_O     16384
#define ET_O     98304
#define MB_O     114688
#define TP_O     114712
#define TC_SMEM  114720

#if TC_ON
static constexpr uint64_t DESC_BASE_SW64 =
    (uint64_t(4) << 61) | (uint64_t(1) << 46) | (uint64_t(32) << 32) | (uint64_t(1) << 16);
__device__ __forceinline__ uint64_t mk_desc64(uint32_t addr) {
    return DESC_BASE_SW64 | ((uint64_t)(addr >> 4) & 0x3FFF);
}
__device__ __forceinline__ void mma_f16_ss(uint32_t d, uint64_t ad, uint64_t bd,
                                           uint32_t idesc, uint32_t en) {
    asm volatile(
        "{\n\t.reg .pred p;\n\t"
        "setp.ne.u32 p, %5, 0;\n\t"
        "tcgen05.mma.cta_group::1.kind::f16 [%0], %1, %2, %3, {%4, %4, %4, %4}, p;\n\t}"
        :: "r"(d), "l"(ad), "l"(bd), "r"(idesc), "r"(0u), "r"(en) : "memory");
}
#define TC_ALLOC(sa, n)   asm volatile("tcgen05.alloc.cta_group::1.sync.aligned.shared::cta.b32 [%0], %1;" :: "r"(sa), "r"(n) : "memory")
#define TC_DEALLOC(t, n)  asm volatile("tcgen05.dealloc.cta_group::1.sync.aligned.b32 %0, %1;" :: "r"(t), "r"(n))
#define TC_RELINQ()       asm volatile("tcgen05.relinquish_alloc_permit.cta_group::1.sync.aligned;")
#define TC_COMMIT(mb)     asm volatile("tcgen05.commit.cta_group::1.mbarrier::arrive::one.shared::cluster.b64 [%0];" :: "r"(mb) : "memory")
#define TC_WAIT_LD()      asm volatile("tcgen05.wait::ld.sync.aligned;" ::: "memory")
#define TC_FENCE_AFTER()  asm volatile("tcgen05.fence::after_thread_sync;" ::: "memory")
#define FENCE_PROXY()     asm volatile("fence.proxy.async;" ::: "memory")
#define MBAR_INIT(mb, n)  asm volatile("mbarrier.init.shared.b64 [%0], %1;" :: "r"(mb), "r"(n) : "memory")
#define MBAR_WAIT(mb, ph) do {                                                            \
    uint32_t _m = (mb), _p = (ph), _d;                                                    \
    asm volatile("{\n\t.reg .pred p;\n\t"                                                 \
        "mbarrier.try_wait.parity.acquire.cta.shared::cta.b64 p, [%1], %2;\n\t"           \
        "selp.b32 %0, 1, 0, p;\n\t}" : "=r"(_d) : "r"(_m), "r"(_p) : "memory");           \
    if (!_d) {                                                                            \
        asm volatile("{\n\t.reg .pred P1;\n\t"                                            \
            "W%=:\n\t"                                                                    \
            "mbarrier.try_wait.parity.acquire.cta.shared::cta.b64 P1, [%0], %1, 0x989680;\n\t" \
            "@P1 bra.uni D%=;\n\t"                                                        \
            "bra.uni W%=;\n\t"                                                            \
            "D%=:\n\t}" :: "r"(_m), "r"(_p) : "memory");                                  \
    }                                                                                     \
} while (0)
#define STS128A(a, r0, r1, r2, r3) asm volatile("st.shared.v4.b32 [%0], {%1,%2,%3,%4};" :: "r"(a), "r"(r0), "r"(r1), "r"(r2), "r"(r3) : "memory")
#define LDTM_X32(r, t) \
    asm volatile("tcgen05.ld.sync.aligned.32x32b.x32.b32 " \
        "{%0,%1,%2,%3,%4,%5,%6,%7,%8,%9,%10,%11,%12,%13,%14,%15," \
        "%16,%17,%18,%19,%20,%21,%22,%23,%24,%25,%26,%27,%28,%29,%30,%31}, [%32];" \
        : "=r"((r)[0]),"=r"((r)[1]),"=r"((r)[2]),"=r"((r)[3]),"=r"((r)[4]),"=r"((r)[5]),"=r"((r)[6]),"=r"((r)[7]), \
          "=r"((r)[8]),"=r"((r)[9]),"=r"((r)[10]),"=r"((r)[11]),"=r"((r)[12]),"=r"((r)[13]),"=r"((r)[14]),"=r"((r)[15]), \
          "=r"((r)[16]),"=r"((r)[17]),"=r"((r)[18]),"=r"((r)[19]),"=r"((r)[20]),"=r"((r)[21]),"=r"((r)[22]),"=r"((r)[23]), \
          "=r"((r)[24]),"=r"((r)[25]),"=r"((r)[26]),"=r"((r)[27]),"=r"((r)[28]),"=r"((r)[29]),"=r"((r)[30]),"=r"((r)[31]) \
        : "r"(t))

// idesc: F32 out | F16 a | F16 b | N=256 | M=128
static constexpr uint32_t IDESC =
    (1u << 4) | ((FOUT / 8) << 17) | (8u << 24);

// ---------------------------------------------------------------------------
// Attention: 128 CTAs = 32 row-blocks (TM=256) x 4 j-splits. 512 threads.
// R12 skeleton; single fp16 MMA pass (4 dispatches/stage); adj prefetch dist 2.
// ---------------------------------------------------------------------------
__global__ __launch_bounds__(ATHREADS, 1) void k_attn_tc(const int* __restrict__ adj) {
    extern __shared__ __align__(1024) char smem_raw[];
    const uint32_t sb = smem_u32(smem_raw);
    const int tid = threadIdx.x;
    const int wid = tid >> 5;
    const int split = blockIdx.x & 3;
    const int i0 = (blockIdx.x >> 2) * TM;
    const int jbase = split * JSPAN;

    if (wid == 0) TC_ALLOC(sb + TP_O, 512);
    if (tid == 0) {
        MBAR_INIT(sb + MB_O + 0, 1);
        MBAR_INIT(sb + MB_O + 8, 1);
        MBAR_INIT(sb + MB_O + 16, 1);
    }
    // E-table: et[j] = (exp(f2_j), exp(0.2*f2_j)) fp32, 2048 j = 16 KB
    float2* et = (float2*)(smem_raw + ET_O);
    {
        float4 f2v = *(const float4*)&g_f2[jbase + tid * 4];
        float4 lo4, hi4;
        lo4.x = exp2f(f2v.x * LOG2E);          lo4.y = exp2f(f2v.x * (ALPHA * LOG2E));
        lo4.z = exp2f(f2v.y * LOG2E);          lo4.w = exp2f(f2v.y * (ALPHA * LOG2E));
        hi4.x = exp2f(f2v.z * LOG2E);          hi4.y = exp2f(f2v.z * (ALPHA * LOG2E));
        hi4.z = exp2f(f2v.w * LOG2E);          hi4.w = exp2f(f2v.w * (ALPHA * LOG2E));
        *(float4*)&et[tid * 4]     = lo4;
        *(float4*)&et[tid * 4 + 2] = hi4;
    }
    __syncthreads();
    const uint32_t tmem = *(const uint32_t*)(smem_raw + TP_O);

    const int row = tid >> 1, half = tid & 1;
    const float f1r = g_f1[i0 + row];
    const float gm = gmax_decode(g_gmax_key);
    const float Ms = f1r + gm;
    const float M = fmaxf(Ms, ALPHA * Ms);
    const float Ai = exp2f((f1r - M) * LOG2E);
    const float Ci = exp2f((ALPHA * f1r - M) * LOG2E);
    const int* adjrow = adj + (size_t)(i0 + row) * N_NODES + jbase + half * 16;
    float zreg = 0.f;

    const int bf = tid >> 1, bkk = tid & 1;

    // prologue: B(0) -> buf0
    {
        const char* sh = (const char*)&g_WhT_hi[(size_t)bf * N_NODES + jbase + bkk * 16];
        #pragma unroll
        for (int q = 0; q < 2; q++) {
            uint32_t d = swz64((uint32_t)(bf * 64 + bkk * 32 + q * 16));
            CP16(sb + BH_O + d, sh + q * 16);
        }
        CP_COMMIT();
    }
    // adj double-buffered register prefetch (distance 2)
    int4 areg[2][4];
    {
        const int4* a0 = (const int4*)adjrow;
        const int4* a1 = (const int4*)(adjrow + KC);
        #pragma unroll
        for (int q = 0; q < 4; q++) { areg[0][q] = a0[q]; areg[1][q] = a1[q]; }
    }

    for (int s = 0; s < STAGES; s++) {
        const int b = s % 3;
        const int bn = (s + 1) % 3;
        const int ab_idx = s & 1;

        if (s >= 2) MBAR_WAIT(sb + MB_O + bn * 8, ((s - 2) / 3) & 1);

        if (s + 1 < STAGES) {
            const size_t jcol = (size_t)jbase + (s + 1) * KC + bkk * 16;
            const uint32_t bh = sb + bn * BUF_SZ + BH_O;
            const char* sh = (const char*)&g_WhT_hi[(size_t)bf * N_NODES + jcol];
            #pragma unroll
            for (int q = 0; q < 2; q++) {
                uint32_t d = swz64((uint32_t)(bf * 64 + bkk * 32 + q * 16));
                CP16(bh + d, sh + q * 16);
            }
        }
        CP_COMMIT();

        // P tile: 16 j, factorized-exp + max trick, fp16 store
        {
            const uint32_t ah = sb + b * BUF_SZ + AH_O;
            const float4* ev = (const float4*)&et[s * KC + half * 16];
            #pragma unroll
            for (int t2 = 0; t2 < 2; t2++) {
                float p[8];
                #pragma unroll
                for (int q = 0; q < 2; q++) {
                    float4 e0 = ev[t2 * 4 + q * 2];
                    float4 e1 = ev[t2 * 4 + q * 2 + 1];
                    int4 av = areg[ab_idx][t2 * 2 + q];
                    float p0 = fmaxf(e0.x * Ai, e0.y * Ci);
                    float p1 = fmaxf(e0.z * Ai, e0.w * Ci);
                    float p2 = fmaxf(e1.x * Ai, e1.y * Ci);
                    float p3 = fmaxf(e1.z * Ai, e1.w * Ci);
                    p[q * 4 + 0] = (av.x > 0) ? p0 : 0.f;
                    p[q * 4 + 1] = (av.y > 0) ? p1 : 0.f;
                    p[q * 4 + 2] = (av.z > 0) ? p2 : 0.f;
                    p[q * 4 + 3] = (av.w > 0) ? p3 : 0.f;
                    zreg += p[q * 4 + 0] + p[q * 4 + 1] + p[q * 4 + 2] + p[q * 4 + 3];
                }
                uint32_t hw0 = f16x2_pack(p[0], p[1]);
                uint32_t hw1 = f16x2_pack(p[2], p[3]);
                uint32_t hw2 = f16x2_pack(p[4], p[5]);
                uint32_t hw3 = f16x2_pack(p[6], p[7]);
                uint32_t so = swz64((uint32_t)(row * 64 + half * 32 + t2 * 16));
                STS128A(ah + so, hw0, hw1, hw2, hw3);
            }
        }

        // prefetch adj(s+2) into the buffer just consumed (same parity)
        if (s + 2 < STAGES) {
            const int4* ap = (const int4*)(adjrow + (size_t)(s + 2) * KC);
            #pragma unroll
            for (int q = 0; q < 4; q++) areg[ab_idx][q] = ap[q];
        }

        CP_WAIT1();
        __syncthreads();

        if (tid == 0) {
            FENCE_PROXY();
            const uint32_t ab = sb + b * BUF_SZ;
            uint64_t dah = mk_desc64(ab + AH_O);
            uint64_t dbh = mk_desc64(ab + BH_O);
            #pragma unroll
            for (int rb = 0; rb < 2; rb++)
                #pragma unroll
                for (int k = 0; k < 2; k++) {
                    uint32_t en = !(s == 0 && k == 0);
                    mma_f16_ss(tmem + rb * 256,
                               dah + rb * 512 + k * 2,
                               dbh + k * 2, IDESC, en);
                }
            TC_COMMIT(sb + MB_O + b * 8);
        }
    }

    zreg += __shfl_xor_sync(~0u, zreg, 1);
    if (!half) g_Zp[split * N_NODES + i0 + row] = zreg;

    MBAR_WAIT(sb + MB_O + ((STAGES - 1) % 3) * 8, ((STAGES - 1) / 3) & 1);
    TC_FENCE_AFTER();

    // readout: 16 warps; rb = (wid>>2)&1, colhalf = wid>>3, subpartition = wid&3
    {
        const int rb = (wid >> 2) & 1;
        const int colhalf = wid >> 3;
        const int sw = wid & 3;
        const int lane = tid & 31;
        float* up = &g_Up[((size_t)split * N_NODES + i0 + rb * 128 + sw * 32 + lane) * FOUT
                          + colhalf * 128];
        const uint32_t tbase = tmem + rb * 256 + colhalf * 128;
        #pragma unroll
        for (int cb = 0; cb < 128; cb += 32) {
            uint32_t r[32];
            LDTM_X32(r, tbase + cb);
            TC_WAIT_LD();
            #pragma unroll
            for (int c = 0; c < 32; c += 4)
                *(float4*)&up[cb + c] = make_float4(
                    __uint_as_float(r[c]), __uint_as_float(r[c + 1]),
                    __uint_as_float(r[c + 2]), __uint_as_float(r[c + 3]));
        }
    }
    __syncthreads();
    if (wid == 0) { TC_RELINQ(); TC_DEALLOC(tmem, 512); }
}

// TC mode: combine + ELU. grid 1024 x 256thr; 8 rows/block; MLP 8.
__global__ __launch_bounds__(256, 4) void k_attn_fb(const int* __restrict__ adj,
                                                    float* __restrict__ out) {
    __shared__ float invz[8];
    const size_t NF = (size_t)N_NODES * FOUT;
    const int i0 = blockIdx.x * 8;
    const int tid = threadIdx.x;
    if (tid < 8) {
        int r = i0 + tid;
        float z = g_Zp[r] + g_Zp[N_NODES + r] + g_Zp[2 * N_NODES + r] + g_Zp[3 * N_NODES + r];
        invz[tid] = 1.f / z;
    }
    __syncthreads();
    #pragma unroll
    for (int k = 0; k < 2; k++) {
        int lin = tid + k * 256;
        int r = lin >> 6, c4 = (lin & 63) * 4;
        size_t off = (size_t)(i0 + r) * FOUT + c4;
        float4 u0 = *(const float4*)&g_Up[off];
        float4 u1 = *(const float4*)&g_Up[NF + off];
        float4 u2 = *(const float4*)&g_Up[2 * NF + off];
        float4 u3 = *(const float4*)&g_Up[3 * NF + off];
        float iz = invz[r];
        float4 v;
        v.x = (u0.x + u1.x + u2.x + u3.x) * iz;
        v.y = (u0.y + u1.y + u2.y + u3.y) * iz;
        v.z = (u0.z + u1.z + u2.z + u3.z) * iz;
        v.w = (u0.w + u1.w + u2.w + u3.w) * iz;
        v.x = v.x > 0.f ? v.x : expm1f(v.x);
        v.y = v.y > 0.f ? v.y : expm1f(v.y);
        v.z = v.z > 0.f ? v.z : expm1f(v.z);
        v.w = v.w > 0.f ? v.w : expm1f(v.w);
        *(float4*)&out[off] = v;
    }
}

#else  // ================== CUDA-CORE FALLBACK PATH ==========================

__global__ __launch_bounds__(ATHREADS, 1) void k_attn_tc(const int* __restrict__ adj) {}

#define FB_WHS(buf) ((buf) * 8192)
#define FB_PS(buf)  (16384 + (buf) * 1152)
#define FB_ZR       18688

__global__ __launch_bounds__(256, 2) void k_attn_fb(const int* __restrict__ adj,
                                                    float* __restrict__ out) {
    extern __shared__ __align__(16) float fsm[];
    const uint32_t sb = smem_u32(fsm);
    const int tid = threadIdx.x;
    const int i0 = blockIdx.x * 32;
    if (i0 >= N_NODES) return;   // wide grid in tc mode
    const int tx = tid & 63;
    const int ty = tid >> 6;
    const int pr = tid >> 3;
    const int pc = (tid & 7) * 4;

    const float f1r = g_f1[i0 + pr];
    const float gm = gmax_decode(g_gmax_key);
    const float Ms = f1r + gm;
    const float M = fmaxf(Ms, ALPHA * Ms);
    const size_t arowbase = (size_t)(i0 + pr) * N_NODES;

    u64 acc[4][4] = {};
    float zreg = 0.f;

    {
        #pragma unroll
        for (int l = 0; l < 8; l++) {
            int lin = l * 256 + tid;
            int row = lin >> 6, c4 = lin & 63;
            CP16(sb + (uint32_t)(FB_WHS(0) + row * 256 + c4 * 4) * 4,
                 (const char*)&g_Wh[(size_t)row * FOUT + c4 * 4]);
        }
        CP_COMMIT();
        int4 av = *(const int4*)(adj + arowbase + pc);
        float4 fv = *(const float4*)&g_f2[pc];
        const int am[4] = {av.x, av.y, av.z, av.w};
        const float ff[4] = {fv.x, fv.y, fv.z, fv.w};
        #pragma unroll
        for (int c = 0; c < 4; c++) {
            float e = f1r + ff[c];
            e = fmaxf(e, ALPHA * e);
            float p = (am[c] > 0) ? __expf(e - M) : 0.f;
            zreg += p;
            fsm[FB_PS(0) + (pc + c) * 36 + pr] = p;
        }
        CP_WAIT0();
        __syncthreads();
    }

    for (int s = 0; s < 256; s++) {
        const int cur = s & 1;
        int4 a_pf; float4 f2_pf;
        const bool more = (s < 255);
        if (more) {
            const int j0n = (s + 1) * 32;
            #pragma unroll
            for (int l = 0; l < 8; l++) {
                int lin = l * 256 + tid;
                int row = lin >> 6, c4 = lin & 63;
                CP16(sb + (uint32_t)(FB_WHS(cur ^ 1) + row * 256 + c4 * 4) * 4,
                     (const char*)&g_Wh[(size_t)(j0n + row) * FOUT + c4 * 4]);
            }
            CP_COMMIT();
            a_pf = *(const int4*)(adj + arowbase + j0n + pc);
            f2_pf = *(const float4*)&g_f2[j0n + pc];
        }

        const float* Whc = &fsm[FB_WHS(cur)];
        const float* Psc = &fsm[FB_PS(cur)];
        #pragma unroll
        for (int jj = 0; jj < 32; jj++) {
            const u64* pp = (const u64*)&Psc[jj * 36 + ty * 8];
            u64 p01 = pp[0], p23 = pp[1], p45 = pp[2], p67 = pp[3];
            float4 w4 = *(const float4*)&Whc[jj * 256 + tx * 4];
            u64 wx = pack2(w4.x, w4.x), wy = pack2(w4.y, w4.y);
            u64 wz = pack2(w4.z, w4.z), ww = pack2(w4.w, w4.w);
            ffma2(acc[0][0], p01, wx); ffma2(acc[0][1], p01, wy);
            ffma2(acc[0][2], p01, wz); ffma2(acc[0][3], p01, ww);
            ffma2(acc[1][0], p23, wx); ffma2(acc[1][1], p23, wy);
            ffma2(acc[1][2], p23, wz); ffma2(acc[1][3], p23, ww);
            ffma2(acc[2][0], p45, wx); ffma2(acc[2][1], p45, wy);
            ffma2(acc[2][2], p45, wz); ffma2(acc[2][3], p45, ww);
            ffma2(acc[3][0], p67, wx); ffma2(acc[3][1], p67, wy);
            ffma2(acc[3][2], p67, wz); ffma2(acc[3][3], p67, ww);
        }

        if (more) {
            const int am[4] = {a_pf.x, a_pf.y, a_pf.z, a_pf.w};
            const float ff[4] = {f2_pf.x, f2_pf.y, f2_pf.z, f2_pf.w};
            #pragma unroll
            for (int c = 0; c < 4; c++) {
                float e = f1r + ff[c];
                e = fmaxf(e, ALPHA * e);
                float p = (am[c] > 0) ? __expf(e - M) : 0.f;
                zreg += p;
                fsm[FB_PS(cur ^ 1) + (pc + c) * 36 + pr] = p;
            }
            CP_WAIT0();
        }
        __syncthreads();
    }

    zreg += __shfl_xor_sync(~0u, zreg, 4);
    zreg += __shfl_xor_sync(~0u, zreg, 2);
    zreg += __shfl_xor_sync(~0u, zreg, 1);
    if ((tid & 7) == 0) fsm[FB_ZR + pr] = zreg;
    __syncthreads();

    #pragma unroll
    for (int r = 0; r < 4; r++) {
        int row_e = ty * 8 + 2 * r;
        float invZe = 1.f / fsm[FB_ZR + row_e];
        float invZo = 1.f / fsm[FB_ZR + row_e + 1];
        float e0, o0, e1, o1, e2, o2, e3, o3;
        unpack2(acc[r][0], e0, o0); unpack2(acc[r][1], e1, o1);
        unpack2(acc[r][2], e2, o2); unpack2(acc[r][3], e3, o3);
        e0 *= invZe; e1 *= invZe; e2 *= invZe; e3 *= invZe;
        o0 *= invZo; o1 *= invZo; o2 *= invZo; o3 *= invZo;
        float4 ve, vo;
        ve.x = e0 > 0.f ? e0 : expm1f(e0);
        ve.y = e1 > 0.f ? e1 : expm1f(e1);
        ve.z = e2 > 0.f ? e2 : expm1f(e2);
        ve.w = e3 > 0.f ? e3 : expm1f(e3);
        vo.x = o0 > 0.f ? o0 : expm1f(o0);
        vo.y = o1 > 0.f ? o1 : expm1f(o1);
        vo.z = o2 > 0.f ? o2 : expm1f(o2);
        vo.w = o3 > 0.f ? o3 : expm1f(o3);
        *(float4*)&out[(size_t)(i0 + row_e + 0) * FOUT + tx * 4] = ve;
        *(float4*)&out[(size_t)(i0 + row_e + 1) * FOUT + tx * 4] = vo;
    }
}
#endif  // TC_ON

#define FB_SMEM 74880

// ---------------------------------------------------------------------------
extern "C" void kernel_launch(void* const* d_in, const int* in_sizes, int n_in,
                              void* d_out, int out_size) {
    const float* h   = (const float*)d_in[0];
    const int*   adj = (const int*)d_in[1];
    const float* W   = (const float*)d_in[2];
    const float* a   = (const float*)d_in[3];
    float* out = (float*)d_out;

    cudaFuncSetAttribute(k_attn_tc, cudaFuncAttributeMaxDynamicSharedMemorySize, TC_SMEM);
    cudaFuncSetAttribute(k_attn_fb, cudaFuncAttributeMaxDynamicSharedMemorySize, FB_SMEM);

    dim3 g1(N_NODES / 64, FOUT / 64);
    k_gemm_wh<<<g1, 256>>>(h, W);                                    // + fused fp16 split
    k_f12<<<N_NODES / 8, 256>>>(a);
    k_attn_tc<<<(N_NODES / TM) * SPLITS, ATHREADS, TC_SMEM>>>(adj);  // 128 CTAs
    k_attn_fb<<<N_NODES / 8, 256, FB_SMEM>>>(adj, out);              // combiner (tc) / full fb
}